// round 14
// baseline (speedup 1.0000x reference)
#include <cuda_runtime.h>
#include <cuda_fp16.h>
#include <math.h>

#define NB 8
#define LQ 2048
#define DD 512
#define DECAYF 0.2f
#define KQS 520      // Q/K smem stride (fp16 elems) -> 1040 B
#define PS2 40       // P smem stride (fp16 elems) -> 80 B

// attn smem byte offsets (fp16, Q 64 rows, double-buffered 32-row K)
#define OFF_Q  0                          // 64*520*2 = 66560
#define OFF_K0 66560
#define OFF_K1 99840
#define OFF_P  133120                     // 64*40*2 = 5120
#define OFF_RED 138240                    // 256*4
#define SMEM_ATTN (OFF_RED + 1024)

// fusion tiling: CTA 128x64, warp 32x32, K-chunk 64, double-buffered cp.async
#define FROWB 144
#define F_A 0
#define F_B 18432
#define F_BUF 27648
#define SMEM_FUS (2 * F_BUF)
#define FNCH 16

// Scratch (device globals: allocation-free per harness rules)
__device__ __half g_Xs[NB * LQ * DD];
__device__ __half g_Xt[NB * LQ * DD];
__device__ __half g_cat[NB * LQ * 2 * DD];
__device__ __half g_W[DD * 2 * DD];

// ---------------------------------------------------------------------------
// mma / ldmatrix / cp.async helpers (legacy mma.sync — tcgen05 rejected by
// this toolchain's sm_103 non-'a' target)
// ---------------------------------------------------------------------------
__device__ __forceinline__ void ldmx4(unsigned* r, unsigned a) {
    asm volatile("ldmatrix.sync.aligned.m8n8.x4.shared.b16 {%0,%1,%2,%3}, [%4];"
        : "=r"(r[0]), "=r"(r[1]), "=r"(r[2]), "=r"(r[3]) : "r"(a));
}
__device__ __forceinline__ void ldmx2(unsigned* r, unsigned a) {
    asm volatile("ldmatrix.sync.aligned.m8n8.x2.shared.b16 {%0,%1}, [%2];"
        : "=r"(r[0]), "=r"(r[1]) : "r"(a));
}
__device__ __forceinline__ void ldmx2t(unsigned* r, unsigned a) {
    asm volatile("ldmatrix.sync.aligned.m8n8.x2.trans.shared.b16 {%0,%1}, [%2];"
        : "=r"(r[0]), "=r"(r[1]) : "r"(a));
}
__device__ __forceinline__ void mma_f16(float* c, const unsigned* a, const unsigned* b) {
    asm volatile("mma.sync.aligned.m16n8k16.row.col.f32.f16.f16.f32 "
        "{%0,%1,%2,%3}, {%4,%5,%6,%7}, {%8,%9}, {%0,%1,%2,%3};"
        : "+f"(c[0]), "+f"(c[1]), "+f"(c[2]), "+f"(c[3])
        : "r"(a[0]), "r"(a[1]), "r"(a[2]), "r"(a[3]), "r"(b[0]), "r"(b[1]));
}
__device__ __forceinline__ void cpa16(unsigned saddr, const void* g) {
    asm volatile("cp.async.cg.shared.global [%0], [%1], 16;"
        :: "r"(saddr), "l"(g) : "memory");
}
#define CPA_COMMIT() asm volatile("cp.async.commit_group;" ::: "memory")
#define CPA_WAIT1()  asm volatile("cp.async.wait_group 1;" ::: "memory")
#define CPA_WAIT0()  asm volatile("cp.async.wait_group 0;" ::: "memory")

__device__ __forceinline__ unsigned packh2(float a, float b) {
    __half2 h = __floats2half2_rn(a, b);
    return *(unsigned*)&h;
}
__device__ __forceinline__ float warpSum(float v) {
    #pragma unroll
    for (int o = 16; o > 0; o >>= 1) v += __shfl_xor_sync(0xffffffffu, v, o);
    return v;
}

// ---------------------------------------------------------------------------
// Warp-level routing (elementwise over 16 channels per lane + warp sums)
// ---------------------------------------------------------------------------
__device__ __forceinline__ void routing16(const float* u0, const float* u1, float* vout) {
    float b0 = 0.f, b1 = 0.f;
    #pragma unroll
    for (int it = 0; it < 3; it++) {
        float mx = fmaxf(b0, b1);
        float e0 = __expf(b0 - mx), e1 = __expf(b1 - mx);
        float inv = 1.f / (e0 + e1);
        float c0 = e0 * inv, c1 = e1 * inv;
        float loc = 0.f;
        #pragma unroll
        for (int i = 0; i < 16; i++) {
            float s = c0 * u0[i] + c1 * u1[i];
            vout[i] = s;
            loc = fmaf(s, s, loc);
        }
        float n2 = warpSum(loc);
        float nrm = sqrtf(n2);
        float scl = n2 / ((1.f + n2) * (nrm + 1e-9f));
        #pragma unroll
        for (int i = 0; i < 16; i++) vout[i] *= scl;
        if (it < 2) {
            float l0 = 0.f, l1 = 0.f;
            #pragma unroll
            for (int i = 0; i < 16; i++) {
                l0 = fmaf(u0[i], vout[i], l0);
                l1 = fmaf(u1[i], vout[i], l1);
            }
            b0 += warpSum(l0);
            b1 += warpSum(l1);
        }
    }
}

// ---------------------------------------------------------------------------
// Kernel 1: convs + routing, warp-per-row, float4 loads
// channel mapping: idx (i,k) -> c = lane*4 + i*128 + k   (elementwise-safe)
// ---------------------------------------------------------------------------
__global__ void __launch_bounds__(256) prep_kernel(const float* __restrict__ x,
                                                   const float* __restrict__ w3,
                                                   const float* __restrict__ w5) {
    int wid = threadIdx.x >> 5, lane = threadIdx.x & 31;
    int row = blockIdx.x * 8 + wid;
    int n = row >> 11, l = row & 2047;
    const float* xb = x + (size_t)n * LQ * DD;

    float xv[16], t3[16], t5[16];
    #pragma unroll
    for (int i = 0; i < 4; i++) {
        int c = lane * 4 + i * 128;
        float a3[4] = {0.f, 0.f, 0.f, 0.f};
        float a5[4] = {0.f, 0.f, 0.f, 0.f};
        float xl[4] = {0.f, 0.f, 0.f, 0.f};
        #pragma unroll
        for (int j = 0; j < 5; j++) {
            int ll = l - 4 + j;
            float4 xx = make_float4(0.f, 0.f, 0.f, 0.f);
            if (ll >= 0) xx = *(const float4*)(xb + (size_t)ll * DD + c);
            xl[0] = xx.x; xl[1] = xx.y; xl[2] = xx.z; xl[3] = xx.w;
            #pragma unroll
            for (int k = 0; k < 4; k++) {
                a5[k] = fmaf(__ldg(w5 + (c + k) * 5 + j), xl[k], a5[k]);
                if (j >= 2) a3[k] = fmaf(__ldg(w3 + (c + k) * 3 + (j - 2)), xl[k], a3[k]);
            }
        }
        #pragma unroll
        for (int k = 0; k < 4; k++) {
            xv[i * 4 + k] = xl[k];   // j==4 pass has ll == l >= 0
            t3[i * 4 + k] = a3[k];
            t5[i * 4 + k] = a5[k];
        }
    }

    float u0[16], u1[16], v[16];
    #pragma unroll
    for (int i = 0; i < 16; i++) { u0[i] = xv[i] - t3[i]; u1[i] = xv[i] - t5[i]; }
    routing16(u0, u1, v);
    #pragma unroll
    for (int i = 0; i < 4; i++) {
        uint2 st = make_uint2(packh2(v[i * 4 + 0], v[i * 4 + 1]),
                              packh2(v[i * 4 + 2], v[i * 4 + 3]));
        *(uint2*)&g_Xs[(size_t)row * DD + lane * 4 + i * 128] = st;
    }
    routing16(t3, t5, v);
    #pragma unroll
    for (int i = 0; i < 4; i++) {
        uint2 st = make_uint2(packh2(v[i * 4 + 0], v[i * 4 + 1]),
                              packh2(v[i * 4 + 2], v[i * 4 + 3]));
        *(uint2*)&g_Xt[(size_t)row * DD + lane * 4 + i * 128] = st;
    }
}

__global__ void wsplit_kernel(const float* __restrict__ W) {
    int i = blockIdx.x * 256 + threadIdx.x;
    g_W[i] = __float2half(W[i]);
}

// ---------------------------------------------------------------------------
// attention: windowed flash, fp16, fixed-shift softmax, Q-tile 64 rows,
// cp.async K prefetch, 4-way split QK chains.
// grid=(32, 8, 2), 512 threads (16 warps: rg=w&3 row group, cg=w>>2 col group)
// K window per Q tile: rows [q0-64, q0+64) -> min dropped distance 65.
// ---------------------------------------------------------------------------
__device__ __forceinline__ void attn_fillK(unsigned sdst, const __half* X, int kt, int tid) {
    #pragma unroll
    for (int i0 = 0; i0 < 4; i0++) {
        int i = tid + i0 * 512;
        int r = i >> 6, c8 = (i & 63) << 3;
        cpa16(sdst + (unsigned)(r * KQS * 2 + c8 * 2), &X[(size_t)(kt * 32 + r) * DD + c8]);
    }
    CPA_COMMIT();
}

__global__ void __launch_bounds__(512, 1) attn_kernel() {
    extern __shared__ char smraw[];
    __half* Qs = (__half*)(smraw + OFF_Q);
    __half* Ps = (__half*)(smraw + OFF_P);
    float* redl = (float*)(smraw + OFF_RED);   // 4 cg-groups x 64 rows

    int zb = blockIdx.z;
    const __half* X = (zb ? g_Xt : g_Xs) + (size_t)blockIdx.y * LQ * DD;
    int n = blockIdx.y;
    int qb = blockIdx.x;
    int tid = threadIdx.x;
    int w = tid >> 5, lane = tid & 31;
    int g4 = lane >> 2, tig = lane & 3, lane7 = lane & 7;
    int q0 = qb * 64;
    int rg = w & 3, cg = w >> 2;

    unsigned sb = (unsigned)__cvta_generic_to_shared(smraw);
    int lrow = lane7 + ((lane >> 3) & 1) * 8;
    int lk8b = (lane >> 4) * 16;
    int bk8b = ((lane >> 3) & 1) * 16;

    unsigned aQ   = sb + OFF_Q + (unsigned)((rg * 16 + lrow) * KQS * 2) + lk8b;
    unsigned koff = (unsigned)((cg * 8 + lane7) * KQS * 2) + bk8b;     // + K buffer base
    unsigned aP   = sb + OFF_P + (unsigned)((rg * 16 + lrow) * PS2 * 2) + lk8b;
    unsigned voff = (unsigned)(lrow * KQS * 2) + (unsigned)(cg * 256); // + K buffer base

    // load Q tile (64 x 512 fp16)
    #pragma unroll
    for (int i0 = 0; i0 < 8; i0++) {
        int i = tid + i0 * 512;
        int r = i >> 6, c8 = (i & 63) << 3;
        *(uint4*)&Qs[r * KQS + c8] = *(const uint4*)&X[(size_t)(q0 + r) * DD + c8];
    }

    float acc[16][4];
    #pragma unroll
    for (int i = 0; i < 16; i++) { acc[i][0] = acc[i][1] = acc[i][2] = acc[i][3] = 0.f; }
    float lsum0 = 0.f, lsum1 = 0.f;

    int par0 = (rg * 16 + g4) * PS2;
    int par1 = (rg * 16 + g4 + 8) * PS2;
    int pc = cg * 8 + 2 * tig;

    int kt_end = 2 * qb + 1;
    int kt0 = (qb >= 1) ? 2 * qb - 2 : 0;
    attn_fillK(sb + OFF_K0, X, kt0, tid);     // prologue prefetch

    for (int kt = kt0; kt <= kt_end; kt++) {
        int cur = (kt - kt0) & 1;
        unsigned kbase = sb + (cur ? OFF_K1 : OFF_K0);
        __syncthreads();                      // prev iter's reads of the other buffer done
        if (kt < kt_end) {
            attn_fillK(sb + (cur ? OFF_K0 : OFF_K1), X, kt + 1, tid);
            CPA_WAIT1();                      // current buffer's group complete
        } else {
            CPA_WAIT0();
        }
        __syncthreads();                      // K tile visible to all warps

        // scores: S = Q K^T, 4 independent accumulator chains
        float s4[4][4];
        #pragma unroll
        for (int i = 0; i < 4; i++) { s4[i][0] = s4[i][1] = s4[i][2] = s4[i][3] = 0.f; }
        unsigned bK = kbase + koff;
        #pragma unroll 8
        for (int ks2 = 0; ks2 < 32; ks2++) {
            unsigned o = ks2 * 32;
            unsigned ah[4], bh[2];
            ldmx4(ah, aQ + o);
            ldmx2(bh, bK + o);
            mma_f16(s4[ks2 & 3], ah, bh);
        }
        float sc[4];
        #pragma unroll
        for (int i = 0; i < 4; i++)
            sc[i] = (s4[0][i] + s4[1][i]) + (s4[2][i] + s4[3][i]);

        int r0 = q0 + rg * 16 + g4, r1 = r0 + 8;
        int c0 = kt * 32 + cg * 8 + 2 * tig, c1 = c0 + 1;
        float p0 = (r0 >= c0) ? __expf(sc[0] - DECAYF * (float)(r0 - c0)) : 0.f;
        float p1 = (r0 >= c1) ? __expf(sc[1] - DECAYF * (float)(r0 - c1)) : 0.f;
        float p2 = (r1 >= c0) ? __expf(sc[2] - DECAYF * (float)(r1 - c0)) : 0.f;
        float p3 = (r1 >= c1) ? __expf(sc[3] - DECAYF * (float)(r1 - c1)) : 0.f;
        lsum0 += p0 + p1;
        lsum1 += p2 + p3;
        *(unsigned*)&Ps[par0 + pc] = packh2(p0, p1);
        *(unsigned*)&Ps[par1 + pc] = packh2(p2, p3);
        __syncthreads();                      // P tile ready

        // PV: O += P V (16 independent chains over this warp's 128-col slice)
        unsigned bV = kbase + voff;
        #pragma unroll
        for (int ks2 = 0; ks2 < 2; ks2++) {
            unsigned ah[4];
            ldmx4(ah, aP + ks2 * 32);
            unsigned vh = bV + (unsigned)(ks2 * 16 * KQS * 2);
            #pragma unroll
            for (int nf = 0; nf < 16; nf++) {
                unsigned bh[2];
                ldmx2t(bh, vh + nf * 16);
                mma_f16(acc[nf], ah, bh);
            }
        }
    }

    // l reduction: quad shuffles (cols within warp) then across 4 cg groups
    lsum0 += __shfl_xor_sync(0xffffffffu, lsum0, 1);
    lsum0 += __shfl_xor_sync(0xffffffffu, lsum0, 2);
    lsum1 += __shfl_xor_sync(0xffffffffu, lsum1, 1);
    lsum1 += __shfl_xor_sync(0xffffffffu, lsum1, 2);
    __syncthreads();
    if (tig == 0) {
        redl[cg * 64 + rg * 16 + g4]     = lsum0;
        redl[cg * 64 + rg * 16 + g4 + 8] = lsum1;
    }
    __syncthreads();
    int row0 = rg * 16 + g4;
    float lt0 = redl[row0] + redl[64 + row0] + redl[128 + row0] + redl[192 + row0];
    float lt1 = redl[row0 + 8] + redl[64 + row0 + 8] + redl[128 + row0 + 8] + redl[192 + row0 + 8];
    float li0 = 1.f / lt0;
    float li1 = 1.f / lt1;

    size_t orow0 = (size_t)(n * LQ + q0 + row0) * (2 * DD);
    size_t orow1 = orow0 + (size_t)8 * (2 * DD);
    #pragma unroll
    for (int nf = 0; nf < 16; nf++) {
        int col = zb * DD + cg * 128 + nf * 8 + 2 * tig;
        *(unsigned*)&g_cat[orow0 + col] = packh2(acc[nf][0] * li0, acc[nf][1] * li0);
        *(unsigned*)&g_cat[orow1 + col] = packh2(acc[nf][2] * li1, acc[nf][3] * li1);
    }
}

// ---------------------------------------------------------------------------
// fusion: out[16384,512] = cat @ W^T + bias, fp16
// CTA 128x64, warp 32x32, K-chunk 64, double-buffered cp.async, 4 CTAs/SM
// ---------------------------------------------------------------------------
__device__ __forceinline__ void fus_fill(unsigned sbuf, int kc, int bm, int bn, int tid) {
    #pragma unroll
    for (int i = 0; i < 4; i++) {
        int idx = tid + i * 256;
        int r = idx >> 3, c8 = (idx & 7) << 3;
        cpa16(sbuf + F_A + (unsigned)(r * FROWB + c8 * 2),
              &g_cat[(size_t)(bm + r) * 1024 + kc * 64 + c8]);
    }
    #pragma unroll
    for (int i = 0; i < 2; i++) {
        int idx = tid + i * 256;
        int r = idx >> 3, c8 = (idx & 7) << 3;
        cpa16(sbuf + F_B + (unsigned)(r * FROWB + c8 * 2),
              &g_W[(size_t)(bn + r) * 1024 + kc * 64 + c8]);
    }
    CPA_COMMIT();
}

__global__ void __launch_bounds__(256, 4) fusion_kernel(const float* __restrict__ bias,
                                                        float* __restrict__ out) {
    extern __shared__ char fsm[];
    unsigned sb = (unsigned)__cvta_generic_to_shared(fsm);
    int tid = threadIdx.x;
    int w = tid >> 5, lane = tid & 31;
    int g4 = lane >> 2, tig = lane & 3, lane7 = lane & 7;
    int rg = w & 3, cg = w >> 2;
    int bm = blockIdx.x * 128;
    int bn = blockIdx.y * 64;
    int lrow = lane7 + ((lane >> 3) & 1) * 8;
    int lk8b = (lane >> 4) * 16;
    int bk8b = ((lane >> 3) & 1) * 16;

    float acc[2][4][4];
    #pragma unroll
    for (int t = 0; t < 2; t++)
        #pragma unroll
        for (int nf = 0; nf < 4; nf++) {
            acc[t][nf][0] = 0.f; acc[t][nf][1] = 0.f;
            acc[t][nf][2] = 0.f; acc[t][nf][3] = 0.f;
        }

    fus_fill(sb, 0, bm, bn, tid);
    fus_fill(sb + F_BUF, 1, bm, bn, tid);

    unsigned aoff0 = (unsigned)((rg * 32 + lrow) * FROWB) + lk8b;
    unsigned aoff1 = (unsigned)((rg * 32 + 16 + lrow) * FROWB) + lk8b;
    unsigned boffs[4];
    #pragma unroll
    for (int nf = 0; nf < 4; nf++)
        boffs[nf] = (unsigned)((cg * 32 + nf * 8 + lane7) * FROWB) + bk8b;

    for (int c = 0; c < FNCH; c++) {
        unsigned base = sb + (unsigned)(c & 1) * F_BUF;
        if (c == FNCH - 1) { CPA_WAIT0(); } else { CPA_WAIT1(); }
        __syncthreads();

        #pragma unroll
        for (int ks = 0; ks < 4; ks++) {
            unsigned ko = (unsigned)(ks * 32);
            unsigned ah0[4], ah1[4];
            ldmx4(ah0, base + F_A + aoff0 + ko);
            ldmx4(ah1, base + F_A + aoff1 + ko);
            unsigned bh[4][2];
            #pragma unroll
            for (int nf = 0; nf < 4; nf++)
                ldmx2(bh[nf], base + F_B + boffs[nf] + ko);
            #pragma unroll
            for (int nf = 0; nf < 4; nf++) {
                mma_f16(acc[0][nf], ah0, bh[nf]);
                mma_f16(acc[1][nf], ah1, bh[nf]);
            }
        }
        __syncthreads();
        if (c + 2 < FNCH) fus_fill(base, c + 2, bm, bn, tid);
    }

    #pragma unroll
    for (int t = 0; t < 2; t++) {
        int orow0 = bm + rg * 32 + t * 16 + g4;
        int orow1 = orow0 + 8;
        #pragma unroll
        for (int nf = 0; nf < 4; nf++) {
            int col = bn + cg * 32 + nf * 8 + 2 * tig;
            float b0v = bias[col], b1v = bias[col + 1];
            *(float2*)&out[(size_t)orow0 * 512 + col] =
                make_float2(acc[t][nf][0] + b0v, acc[t][nf][1] + b1v);
            *(float2*)&out[(size_t)orow1 * 512 + col] =
                make_float2(acc[t][nf][2] + b0v, acc[t][nf][3] + b1v);
        }
    }
}

// ---------------------------------------------------------------------------
extern "C" void kernel_launch(void* const* d_in, const int* in_sizes, int n_in,
                              void* d_out, int out_size) {
    const float* x  = (const float*)d_in[0];
    const float* w3 = (const float*)d_in[1];
    const float* w5 = (const float*)d_in[2];
    const float* fw = (const float*)d_in[3];
    const float* fb = (const float*)d_in[4];
    float* out = (float*)d_out;

    prep_kernel<<<NB * LQ / 8, 256>>>(x, w3, w5);
    wsplit_kernel<<<(DD * 2 * DD) / 256, 256>>>(fw);

    cudaFuncSetAttribute(attn_kernel,
                         cudaFuncAttributeMaxDynamicSharedMemorySize, SMEM_ATTN);
    dim3 ga(LQ / 64, NB, 2);
    attn_kernel<<<ga, 512, SMEM_ATTN>>>();

    cudaFuncSetAttribute(fusion_kernel,
                         cudaFuncAttributeMaxDynamicSharedMemorySize, SMEM_FUS);
    dim3 gf((NB * LQ) / 128, DD / 64);
    fusion_kernel<<<gf, 256, SMEM_FUS>>>(fb, out);
}

// round 15
// speedup vs baseline: 1.1092x; 1.1092x over previous
#include <cuda_runtime.h>
#include <cuda_fp16.h>
#include <math.h>

#define NB 8
#define LQ 2048
#define DD 512
#define DECAYF 0.2f
#define WTILES 2     // window: current + 2 previous 32-row tiles (tail mass < 3.4e-5)
#define KQS 520      // Q/K smem stride (fp16 elems) -> 1040 B
#define PS2 40       // P smem stride (fp16 elems) -> 80 B

// attn smem byte offsets (fp16, 32-row Q, double-buffered 32-row K)
#define OFF_Q  0
#define OFF_K0 33280
#define OFF_K1 66560
#define OFF_P  99840
#define OFF_RED 102400
#define SMEM_ATTN (OFF_RED + 512)

// fusion tiling: CTA 128x64, warp 32x32, K-chunk 64, double-buffered cp.async
#define FROWB 144
#define F_A 0
#define F_B 18432
#define F_BUF 27648
#define SMEM_FUS (2 * F_BUF)
#define FNCH 16

// Scratch (device globals: allocation-free per harness rules)
__device__ __half g_Xs[NB * LQ * DD];
__device__ __half g_Xt[NB * LQ * DD];
__device__ __half g_cat[NB * LQ * 2 * DD];
__device__ __half g_W[DD * 2 * DD];

// ---------------------------------------------------------------------------
// mma / ldmatrix / cp.async helpers (legacy mma.sync — tcgen05 rejected by
// this toolchain's sm_103 non-'a' target)
// ---------------------------------------------------------------------------
__device__ __forceinline__ void ldmx4(unsigned* r, unsigned a) {
    asm volatile("ldmatrix.sync.aligned.m8n8.x4.shared.b16 {%0,%1,%2,%3}, [%4];"
        : "=r"(r[0]), "=r"(r[1]), "=r"(r[2]), "=r"(r[3]) : "r"(a));
}
__device__ __forceinline__ void ldmx2(unsigned* r, unsigned a) {
    asm volatile("ldmatrix.sync.aligned.m8n8.x2.shared.b16 {%0,%1}, [%2];"
        : "=r"(r[0]), "=r"(r[1]) : "r"(a));
}
__device__ __forceinline__ void ldmx2t(unsigned* r, unsigned a) {
    asm volatile("ldmatrix.sync.aligned.m8n8.x2.trans.shared.b16 {%0,%1}, [%2];"
        : "=r"(r[0]), "=r"(r[1]) : "r"(a));
}
__device__ __forceinline__ void mma_f16(float* c, const unsigned* a, const unsigned* b) {
    asm volatile("mma.sync.aligned.m16n8k16.row.col.f32.f16.f16.f32 "
        "{%0,%1,%2,%3}, {%4,%5,%6,%7}, {%8,%9}, {%0,%1,%2,%3};"
        : "+f"(c[0]), "+f"(c[1]), "+f"(c[2]), "+f"(c[3])
        : "r"(a[0]), "r"(a[1]), "r"(a[2]), "r"(a[3]), "r"(b[0]), "r"(b[1]));
}
__device__ __forceinline__ void cpa16(unsigned saddr, const void* g) {
    asm volatile("cp.async.cg.shared.global [%0], [%1], 16;"
        :: "r"(saddr), "l"(g) : "memory");
}
#define CPA_COMMIT() asm volatile("cp.async.commit_group;" ::: "memory")
#define CPA_WAIT1()  asm volatile("cp.async.wait_group 1;" ::: "memory")
#define CPA_WAIT0()  asm volatile("cp.async.wait_group 0;" ::: "memory")

__device__ __forceinline__ unsigned packh2(float a, float b) {
    __half2 h = __floats2half2_rn(a, b);
    return *(unsigned*)&h;
}
__device__ __forceinline__ float warpSum(float v) {
    #pragma unroll
    for (int o = 16; o > 0; o >>= 1) v += __shfl_xor_sync(0xffffffffu, v, o);
    return v;
}

// ---------------------------------------------------------------------------
// Warp-level routing (elementwise over 16 channels per lane + warp sums)
// ---------------------------------------------------------------------------
__device__ __forceinline__ void routing16(const float* u0, const float* u1, float* vout) {
    float b0 = 0.f, b1 = 0.f;
    #pragma unroll
    for (int it = 0; it < 3; it++) {
        float mx = fmaxf(b0, b1);
        float e0 = __expf(b0 - mx), e1 = __expf(b1 - mx);
        float inv = 1.f / (e0 + e1);
        float c0 = e0 * inv, c1 = e1 * inv;
        float loc = 0.f;
        #pragma unroll
        for (int i = 0; i < 16; i++) {
            float s = c0 * u0[i] + c1 * u1[i];
            vout[i] = s;
            loc = fmaf(s, s, loc);
        }
        float n2 = warpSum(loc);
        float nrm = sqrtf(n2);
        float scl = n2 / ((1.f + n2) * (nrm + 1e-9f));
        #pragma unroll
        for (int i = 0; i < 16; i++) vout[i] *= scl;
        if (it < 2) {
            float l0 = 0.f, l1 = 0.f;
            #pragma unroll
            for (int i = 0; i < 16; i++) {
                l0 = fmaf(u0[i], vout[i], l0);
                l1 = fmaf(u1[i], vout[i], l1);
            }
            b0 += warpSum(l0);
            b1 += warpSum(l1);
        }
    }
}

// ---------------------------------------------------------------------------
// Kernel 1: convs + routing, warp-per-row, float4 loads
// channel mapping: idx (i,k) -> c = lane*4 + i*128 + k   (elementwise-safe)
// ---------------------------------------------------------------------------
__global__ void __launch_bounds__(256) prep_kernel(const float* __restrict__ x,
                                                   const float* __restrict__ w3,
                                                   const float* __restrict__ w5) {
    int wid = threadIdx.x >> 5, lane = threadIdx.x & 31;
    int row = blockIdx.x * 8 + wid;
    int n = row >> 11, l = row & 2047;
    const float* xb = x + (size_t)n * LQ * DD;

    float xv[16], t3[16], t5[16];
    #pragma unroll
    for (int i = 0; i < 4; i++) {
        int c = lane * 4 + i * 128;
        float a3[4] = {0.f, 0.f, 0.f, 0.f};
        float a5[4] = {0.f, 0.f, 0.f, 0.f};
        float xl[4] = {0.f, 0.f, 0.f, 0.f};
        #pragma unroll
        for (int j = 0; j < 5; j++) {
            int ll = l - 4 + j;
            float4 xx = make_float4(0.f, 0.f, 0.f, 0.f);
            if (ll >= 0) xx = *(const float4*)(xb + (size_t)ll * DD + c);
            xl[0] = xx.x; xl[1] = xx.y; xl[2] = xx.z; xl[3] = xx.w;
            #pragma unroll
            for (int k = 0; k < 4; k++) {
                a5[k] = fmaf(__ldg(w5 + (c + k) * 5 + j), xl[k], a5[k]);
                if (j >= 2) a3[k] = fmaf(__ldg(w3 + (c + k) * 3 + (j - 2)), xl[k], a3[k]);
            }
        }
        #pragma unroll
        for (int k = 0; k < 4; k++) {
            xv[i * 4 + k] = xl[k];   // j==4 pass has ll == l >= 0
            t3[i * 4 + k] = a3[k];
            t5[i * 4 + k] = a5[k];
        }
    }

    float u0[16], u1[16], v[16];
    #pragma unroll
    for (int i = 0; i < 16; i++) { u0[i] = xv[i] - t3[i]; u1[i] = xv[i] - t5[i]; }
    routing16(u0, u1, v);
    #pragma unroll
    for (int i = 0; i < 4; i++) {
        uint2 st = make_uint2(packh2(v[i * 4 + 0], v[i * 4 + 1]),
                              packh2(v[i * 4 + 2], v[i * 4 + 3]));
        *(uint2*)&g_Xs[(size_t)row * DD + lane * 4 + i * 128] = st;
    }
    routing16(t3, t5, v);
    #pragma unroll
    for (int i = 0; i < 4; i++) {
        uint2 st = make_uint2(packh2(v[i * 4 + 0], v[i * 4 + 1]),
                              packh2(v[i * 4 + 2], v[i * 4 + 3]));
        *(uint2*)&g_Xt[(size_t)row * DD + lane * 4 + i * 128] = st;
    }
}

__global__ void wsplit_kernel(const float* __restrict__ W) {
    int i = blockIdx.x * 256 + threadIdx.x;
    g_W[i] = __float2half(W[i]);
}

// ---------------------------------------------------------------------------
// attention: windowed flash, fp16, fixed-shift softmax, cp.async K prefetch,
// 4-way split QK chains. grid=(64, 8, 2), 256 threads, 2 CTAs/SM  (R12 shape)
// ---------------------------------------------------------------------------
__device__ __forceinline__ void attn_fillK(unsigned sdst, const __half* X, int kb, int tid) {
    #pragma unroll
    for (int i0 = 0; i0 < 8; i0++) {
        int i = tid + i0 * 256;
        int r = i >> 6, c8 = (i & 63) << 3;
        cpa16(sdst + (unsigned)(r * KQS * 2 + c8 * 2), &X[(size_t)(kb * 32 + r) * DD + c8]);
    }
    CPA_COMMIT();
}

__global__ void __launch_bounds__(256, 2) attn_kernel() {
    extern __shared__ char smraw[];
    __half* Qs = (__half*)(smraw + OFF_Q);
    __half* Ps = (__half*)(smraw + OFF_P);
    float* redl = (float*)(smraw + OFF_RED);

    int zb = blockIdx.z;
    const __half* X = (zb ? g_Xt : g_Xs) + (size_t)blockIdx.y * LQ * DD;
    int n = blockIdx.y;
    int qb = blockIdx.x;
    int tid = threadIdx.x;
    int w = tid >> 5, lane = tid & 31;
    int g4 = lane >> 2, tig = lane & 3, lane7 = lane & 7;
    int q0 = qb * 32;
    int rg = w & 1, cg = w >> 1;

    unsigned sb = (unsigned)__cvta_generic_to_shared(smraw);
    int lrow = lane7 + ((lane >> 3) & 1) * 8;
    int lk8b = (lane >> 4) * 16;
    int bk8b = ((lane >> 3) & 1) * 16;

    unsigned aQ   = sb + OFF_Q + (unsigned)((rg * 16 + lrow) * KQS * 2) + lk8b;
    unsigned koff = (unsigned)((cg * 8 + lane7) * KQS * 2) + bk8b;     // + buffer base
    unsigned aP   = sb + OFF_P + (unsigned)((rg * 16 + lrow) * PS2 * 2) + lk8b;
    unsigned voff = (unsigned)(lrow * KQS * 2) + (unsigned)(cg * 256); // + buffer base

    // load Q tile (32 x 512 fp16)
    #pragma unroll
    for (int i0 = 0; i0 < 8; i0++) {
        int i = tid + i0 * 256;
        int r = i >> 6, c8 = (i & 63) << 3;
        *(uint4*)&Qs[r * KQS + c8] = *(const uint4*)&X[(size_t)(q0 + r) * DD + c8];
    }

    float acc[16][4];
    #pragma unroll
    for (int i = 0; i < 16; i++) { acc[i][0] = acc[i][1] = acc[i][2] = acc[i][3] = 0.f; }
    float lsum0 = 0.f, lsum1 = 0.f;

    int par0 = (rg * 16 + g4) * PS2;
    int par1 = (rg * 16 + g4 + 8) * PS2;
    int pc = cg * 8 + 2 * tig;

    int kb0 = (qb >= WTILES) ? qb - WTILES : 0;
    attn_fillK(sb + OFF_K0, X, kb0, tid);     // prologue prefetch

    for (int kb = kb0; kb <= qb; kb++) {
        int cur = (kb - kb0) & 1;
        unsigned kbase = sb + (cur ? OFF_K1 : OFF_K0);
        __syncthreads();                      // prev iter's reads of the other buffer done
        if (kb < qb) {
            attn_fillK(sb + (cur ? OFF_K0 : OFF_K1), X, kb + 1, tid);
            CPA_WAIT1();                      // current buffer's group complete
        } else {
            CPA_WAIT0();
        }
        __syncthreads();                      // K tile visible to all warps

        // scores: S = Q K^T, 4 independent accumulator chains
        float s4[4][4];
        #pragma unroll
        for (int i = 0; i < 4; i++) { s4[i][0] = s4[i][1] = s4[i][2] = s4[i][3] = 0.f; }
        unsigned bK = kbase + koff;
        #pragma unroll 8
        for (int ks2 = 0; ks2 < 32; ks2++) {
            unsigned o = ks2 * 32;
            unsigned ah[4], bh[2];
            ldmx4(ah, aQ + o);
            ldmx2(bh, bK + o);
            mma_f16(s4[ks2 & 3], ah, bh);
        }
        float sc[4];
        #pragma unroll
        for (int i = 0; i < 4; i++)
            sc[i] = (s4[0][i] + s4[1][i]) + (s4[2][i] + s4[3][i]);

        int r0 = q0 + rg * 16 + g4, r1 = r0 + 8;
        int c0 = kb * 32 + cg * 8 + 2 * tig, c1 = c0 + 1;
        float p0 = (r0 >= c0) ? __expf(sc[0] - DECAYF * (float)(r0 - c0)) : 0.f;
        float p1 = (r0 >= c1) ? __expf(sc[1] - DECAYF * (float)(r0 - c1)) : 0.f;
        float p2 = (r1 >= c0) ? __expf(sc[2] - DECAYF * (float)(r1 - c0)) : 0.f;
        float p3 = (r1 >= c1) ? __expf(sc[3] - DECAYF * (float)(r1 - c1)) : 0.f;
        lsum0 += p0 + p1;
        lsum1 += p2 + p3;
        *(unsigned*)&Ps[par0 + pc] = packh2(p0, p1);
        *(unsigned*)&Ps[par1 + pc] = packh2(p2, p3);
        __syncthreads();                      // P tile ready

        // PV: O += P V (16 independent chains)
        unsigned bV = kbase + voff;
        #pragma unroll
        for (int ks2 = 0; ks2 < 2; ks2++) {
            unsigned ah[4];
            ldmx4(ah, aP + ks2 * 32);
            unsigned vh = bV + (unsigned)(ks2 * 16 * KQS * 2);
            #pragma unroll
            for (int nf = 0; nf < 16; nf++) {
                unsigned bh[2];
                ldmx2t(bh, vh + nf * 16);
                mma_f16(acc[nf], ah, bh);
            }
        }
    }

    lsum0 += __shfl_xor_sync(0xffffffffu, lsum0, 1);
    lsum0 += __shfl_xor_sync(0xffffffffu, lsum0, 2);
    lsum1 += __shfl_xor_sync(0xffffffffu, lsum1, 1);
    lsum1 += __shfl_xor_sync(0xffffffffu, lsum1, 2);
    __syncthreads();
    if (tig == 0) {
        redl[cg * 32 + rg * 16 + g4]     = lsum0;
        redl[cg * 32 + rg * 16 + g4 + 8] = lsum1;
    }
    __syncthreads();
    int row0 = rg * 16 + g4;
    float lt0 = redl[row0] + redl[32 + row0] + redl[64 + row0] + redl[96 + row0];
    float lt1 = redl[row0 + 8] + redl[32 + row0 + 8] + redl[64 + row0 + 8] + redl[96 + row0 + 8];
    float li0 = 1.f / lt0;
    float li1 = 1.f / lt1;

    size_t orow0 = (size_t)(n * LQ + q0 + row0) * (2 * DD);
    size_t orow1 = orow0 + (size_t)8 * (2 * DD);
    #pragma unroll
    for (int nf = 0; nf < 16; nf++) {
        int col = zb * DD + cg * 128 + nf * 8 + 2 * tig;
        *(unsigned*)&g_cat[orow0 + col] = packh2(acc[nf][0] * li0, acc[nf][1] * li0);
        *(unsigned*)&g_cat[orow1 + col] = packh2(acc[nf][2] * li1, acc[nf][3] * li1);
    }
}

// ---------------------------------------------------------------------------
// fusion: out[16384,512] = cat @ W^T + bias, fp16
// CTA 128x64, warp 32x32, K-chunk 64, double-buffered cp.async, 4 CTAs/SM
// ---------------------------------------------------------------------------
__device__ __forceinline__ void fus_fill(unsigned sbuf, int kc, int bm, int bn, int tid) {
    #pragma unroll
    for (int i = 0; i < 4; i++) {
        int idx = tid + i * 256;
        int r = idx >> 3, c8 = (idx & 7) << 3;
        cpa16(sbuf + F_A + (unsigned)(r * FROWB + c8 * 2),
              &g_cat[(size_t)(bm + r) * 1024 + kc * 64 + c8]);
    }
    #pragma unroll
    for (int i = 0; i < 2; i++) {
        int idx = tid + i * 256;
        int r = idx >> 3, c8 = (idx & 7) << 3;
        cpa16(sbuf + F_B + (unsigned)(r * FROWB + c8 * 2),
              &g_W[(size_t)(bn + r) * 1024 + kc * 64 + c8]);
    }
    CPA_COMMIT();
}

__global__ void __launch_bounds__(256, 4) fusion_kernel(const float* __restrict__ bias,
                                                        float* __restrict__ out) {
    extern __shared__ char fsm[];
    unsigned sb = (unsigned)__cvta_generic_to_shared(fsm);
    int tid = threadIdx.x;
    int w = tid >> 5, lane = tid & 31;
    int g4 = lane >> 2, tig = lane & 3, lane7 = lane & 7;
    int rg = w & 3, cg = w >> 2;
    int bm = blockIdx.x * 128;
    int bn = blockIdx.y * 64;
    int lrow = lane7 + ((lane >> 3) & 1) * 8;
    int lk8b = (lane >> 4) * 16;
    int bk8b = ((lane >> 3) & 1) * 16;

    float acc[2][4][4];
    #pragma unroll
    for (int t = 0; t < 2; t++)
        #pragma unroll
        for (int nf = 0; nf < 4; nf++) {
            acc[t][nf][0] = 0.f; acc[t][nf][1] = 0.f;
            acc[t][nf][2] = 0.f; acc[t][nf][3] = 0.f;
        }

    fus_fill(sb, 0, bm, bn, tid);
    fus_fill(sb + F_BUF, 1, bm, bn, tid);

    unsigned aoff0 = (unsigned)((rg * 32 + lrow) * FROWB) + lk8b;
    unsigned aoff1 = (unsigned)((rg * 32 + 16 + lrow) * FROWB) + lk8b;
    unsigned boffs[4];
    #pragma unroll
    for (int nf = 0; nf < 4; nf++)
        boffs[nf] = (unsigned)((cg * 32 + nf * 8 + lane7) * FROWB) + bk8b;

    for (int c = 0; c < FNCH; c++) {
        unsigned base = sb + (unsigned)(c & 1) * F_BUF;
        if (c == FNCH - 1) { CPA_WAIT0(); } else { CPA_WAIT1(); }
        __syncthreads();

        #pragma unroll
        for (int ks = 0; ks < 4; ks++) {
            unsigned ko = (unsigned)(ks * 32);
            unsigned ah0[4], ah1[4];
            ldmx4(ah0, base + F_A + aoff0 + ko);
            ldmx4(ah1, base + F_A + aoff1 + ko);
            unsigned bh[4][2];
            #pragma unroll
            for (int nf = 0; nf < 4; nf++)
                ldmx2(bh[nf], base + F_B + boffs[nf] + ko);
            #pragma unroll
            for (int nf = 0; nf < 4; nf++) {
                mma_f16(acc[0][nf], ah0, bh[nf]);
                mma_f16(acc[1][nf], ah1, bh[nf]);
            }
        }
        __syncthreads();
        if (c + 2 < FNCH) fus_fill(base, c + 2, bm, bn, tid);
    }

    #pragma unroll
    for (int t = 0; t < 2; t++) {
        int orow0 = bm + rg * 32 + t * 16 + g4;
        int orow1 = orow0 + 8;
        #pragma unroll
        for (int nf = 0; nf < 4; nf++) {
            int col = bn + cg * 32 + nf * 8 + 2 * tig;
            float b0v = bias[col], b1v = bias[col + 1];
            *(float2*)&out[(size_t)orow0 * 512 + col] =
                make_float2(acc[t][nf][0] + b0v, acc[t][nf][1] + b1v);
            *(float2*)&out[(size_t)orow1 * 512 + col] =
                make_float2(acc[t][nf][2] + b0v, acc[t][nf][3] + b1v);
        }
    }
}

// ---------------------------------------------------------------------------
extern "C" void kernel_launch(void* const* d_in, const int* in_sizes, int n_in,
                              void* d_out, int out_size) {
    const float* x  = (const float*)d_in[0];
    const float* w3 = (const float*)d_in[1];
    const float* w5 = (const float*)d_in[2];
    const float* fw = (const float*)d_in[3];
    const float* fb = (const float*)d_in[4];
    float* out = (float*)d_out;

    prep_kernel<<<NB * LQ / 8, 256>>>(x, w3, w5);
    wsplit_kernel<<<(DD * 2 * DD) / 256, 256>>>(fw);

    cudaFuncSetAttribute(attn_kernel,
                         cudaFuncAttributeMaxDynamicSharedMemorySize, SMEM_ATTN);
    dim3 ga(LQ / 32, NB, 2);
    attn_kernel<<<ga, 256, SMEM_ATTN>>>();

    cudaFuncSetAttribute(fusion_kernel,
                         cudaFuncAttributeMaxDynamicSharedMemorySize, SMEM_FUS);
    dim3 gf((NB * LQ) / 128, DD / 64);
    fusion_kernel<<<gf, 256, SMEM_FUS>>>(fb, out);
}

// round 16
// speedup vs baseline: 1.1923x; 1.0749x over previous
#include <cuda_runtime.h>
#include <cuda_fp16.h>
#include <math.h>

#define NB 8
#define LQ 2048
#define DD 512
#define DECAYF 0.2f
#define WTILES 2     // window: current + 2 previous 32-row tiles (tail mass < 3.4e-5)
#define KQS 520      // Q/K smem stride (fp16 elems) -> 1040 B
#define PS2 40       // P smem stride (fp16 elems) -> 80 B

// attn smem byte offsets (fp16, 32-row Q, double-buffered 32-row K)
#define OFF_Q  0
#define OFF_K0 33280
#define OFF_K1 66560
#define OFF_P  99840
#define OFF_RED 102400
#define SMEM_ATTN (OFF_RED + 512)

// fusion tiling: CTA 128x64, warp 32x32, K-chunk 64, double-buffered cp.async
#define FROWB 144
#define F_A 0
#define F_B 18432
#define F_BUF 27648
#define SMEM_FUS (2 * F_BUF)
#define FNCH 16

// Scratch (device globals: allocation-free per harness rules)
__device__ __half g_Xs[NB * LQ * DD];
__device__ __half g_Xt[NB * LQ * DD];
__device__ __half g_cat[NB * LQ * 2 * DD];
__device__ __half g_W[DD * 2 * DD];

// ---------------------------------------------------------------------------
// mma / ldmatrix / cp.async helpers (legacy mma.sync — tcgen05 rejected by
// this toolchain's sm_103 non-'a' target)
// ---------------------------------------------------------------------------
__device__ __forceinline__ void ldmx4(unsigned* r, unsigned a) {
    asm volatile("ldmatrix.sync.aligned.m8n8.x4.shared.b16 {%0,%1,%2,%3}, [%4];"
        : "=r"(r[0]), "=r"(r[1]), "=r"(r[2]), "=r"(r[3]) : "r"(a));
}
__device__ __forceinline__ void ldmx2(unsigned* r, unsigned a) {
    asm volatile("ldmatrix.sync.aligned.m8n8.x2.shared.b16 {%0,%1}, [%2];"
        : "=r"(r[0]), "=r"(r[1]) : "r"(a));
}
__device__ __forceinline__ void ldmx2t(unsigned* r, unsigned a) {
    asm volatile("ldmatrix.sync.aligned.m8n8.x2.trans.shared.b16 {%0,%1}, [%2];"
        : "=r"(r[0]), "=r"(r[1]) : "r"(a));
}
__device__ __forceinline__ void mma_f16(float* c, const unsigned* a, const unsigned* b) {
    asm volatile("mma.sync.aligned.m16n8k16.row.col.f32.f16.f16.f32 "
        "{%0,%1,%2,%3}, {%4,%5,%6,%7}, {%8,%9}, {%0,%1,%2,%3};"
        : "+f"(c[0]), "+f"(c[1]), "+f"(c[2]), "+f"(c[3])
        : "r"(a[0]), "r"(a[1]), "r"(a[2]), "r"(a[3]), "r"(b[0]), "r"(b[1]));
}
__device__ __forceinline__ void cpa16(unsigned saddr, const void* g) {
    asm volatile("cp.async.cg.shared.global [%0], [%1], 16;"
        :: "r"(saddr), "l"(g) : "memory");
}
#define CPA_COMMIT() asm volatile("cp.async.commit_group;" ::: "memory")
#define CPA_WAIT1()  asm volatile("cp.async.wait_group 1;" ::: "memory")
#define CPA_WAIT0()  asm volatile("cp.async.wait_group 0;" ::: "memory")

__device__ __forceinline__ unsigned packh2(float a, float b) {
    __half2 h = __floats2half2_rn(a, b);
    return *(unsigned*)&h;
}
__device__ __forceinline__ float warpSum(float v) {
    #pragma unroll
    for (int o = 16; o > 0; o >>= 1) v += __shfl_xor_sync(0xffffffffu, v, o);
    return v;
}

// ---------------------------------------------------------------------------
// Warp-level routing (elementwise over 16 channels per lane + warp sums)
// ---------------------------------------------------------------------------
__device__ __forceinline__ void routing16(const float* u0, const float* u1, float* vout) {
    float b0 = 0.f, b1 = 0.f;
    #pragma unroll
    for (int it = 0; it < 3; it++) {
        float mx = fmaxf(b0, b1);
        float e0 = __expf(b0 - mx), e1 = __expf(b1 - mx);
        float inv = 1.f / (e0 + e1);
        float c0 = e0 * inv, c1 = e1 * inv;
        float loc = 0.f;
        #pragma unroll
        for (int i = 0; i < 16; i++) {
            float s = c0 * u0[i] + c1 * u1[i];
            vout[i] = s;
            loc = fmaf(s, s, loc);
        }
        float n2 = warpSum(loc);
        float nrm = sqrtf(n2);
        float scl = n2 / ((1.f + n2) * (nrm + 1e-9f));
        #pragma unroll
        for (int i = 0; i < 16; i++) vout[i] *= scl;
        if (it < 2) {
            float l0 = 0.f, l1 = 0.f;
            #pragma unroll
            for (int i = 0; i < 16; i++) {
                l0 = fmaf(u0[i], vout[i], l0);
                l1 = fmaf(u1[i], vout[i], l1);
            }
            b0 += warpSum(l0);
            b1 += warpSum(l1);
        }
    }
}

// ---------------------------------------------------------------------------
// Kernel 1: convs + routing (R12 scalar form) + folded W fp16 conversion
// grid = 2048 x 256: warp-per-row; thread (b,t) also converts W[b*256+t]
// ---------------------------------------------------------------------------
__global__ void __launch_bounds__(256) prep_kernel(const float* __restrict__ x,
                                                   const float* __restrict__ w3,
                                                   const float* __restrict__ w5,
                                                   const float* __restrict__ W) {
    // folded wsplit: one W element per thread (grid exactly covers 512*1024)
    int widx = blockIdx.x * 256 + threadIdx.x;
    g_W[widx] = __float2half(W[widx]);

    int wid = threadIdx.x >> 5, lane = threadIdx.x & 31;
    int row = blockIdx.x * 8 + wid;
    int n = row >> 11, l = row & 2047;
    const float* xb = x + (size_t)n * LQ * DD;

    float xv[16], t3[16], t5[16];
    #pragma unroll
    for (int i = 0; i < 16; i++) {
        int c = lane + 32 * i;
        float a3 = 0.f, a5 = 0.f, xx = 0.f;
        #pragma unroll
        for (int j = 0; j < 5; j++) {
            int ll = l - 4 + j;
            xx = (ll >= 0) ? __ldg(xb + (size_t)ll * DD + c) : 0.f;
            a5 = fmaf(w5[c * 5 + j], xx, a5);
            if (j >= 2) a3 = fmaf(w3[c * 3 + (j - 2)], xx, a3);
        }
        xv[i] = xx; t3[i] = a3; t5[i] = a5;
    }

    float u0[16], u1[16], v[16];
    #pragma unroll
    for (int i = 0; i < 16; i++) { u0[i] = xv[i] - t3[i]; u1[i] = xv[i] - t5[i]; }
    routing16(u0, u1, v);
    #pragma unroll
    for (int i = 0; i < 16; i++)
        g_Xs[(size_t)row * DD + lane + 32 * i] = __float2half(v[i]);
    routing16(t3, t5, v);
    #pragma unroll
    for (int i = 0; i < 16; i++)
        g_Xt[(size_t)row * DD + lane + 32 * i] = __float2half(v[i]);
}

// ---------------------------------------------------------------------------
// attention: windowed flash, fp16, fixed-shift softmax, cp.async K prefetch,
// 4-way split QK chains. grid=(64, 8, 2), 256 threads, 2 CTAs/SM  (R12 shape)
// ---------------------------------------------------------------------------
__device__ __forceinline__ void attn_fillK(unsigned sdst, const __half* X, int kb, int tid) {
    #pragma unroll
    for (int i0 = 0; i0 < 8; i0++) {
        int i = tid + i0 * 256;
        int r = i >> 6, c8 = (i & 63) << 3;
        cpa16(sdst + (unsigned)(r * KQS * 2 + c8 * 2), &X[(size_t)(kb * 32 + r) * DD + c8]);
    }
    CPA_COMMIT();
}

__global__ void __launch_bounds__(256, 2) attn_kernel() {
    extern __shared__ char smraw[];
    __half* Qs = (__half*)(smraw + OFF_Q);
    __half* Ps = (__half*)(smraw + OFF_P);
    float* redl = (float*)(smraw + OFF_RED);

    int zb = blockIdx.z;
    const __half* X = (zb ? g_Xt : g_Xs) + (size_t)blockIdx.y * LQ * DD;
    int n = blockIdx.y;
    int qb = blockIdx.x;
    int tid = threadIdx.x;
    int w = tid >> 5, lane = tid & 31;
    int g4 = lane >> 2, tig = lane & 3, lane7 = lane & 7;
    int q0 = qb * 32;
    int rg = w & 1, cg = w >> 1;

    unsigned sb = (unsigned)__cvta_generic_to_shared(smraw);
    int lrow = lane7 + ((lane >> 3) & 1) * 8;
    int lk8b = (lane >> 4) * 16;
    int bk8b = ((lane >> 3) & 1) * 16;

    unsigned aQ   = sb + OFF_Q + (unsigned)((rg * 16 + lrow) * KQS * 2) + lk8b;
    unsigned koff = (unsigned)((cg * 8 + lane7) * KQS * 2) + bk8b;     // + buffer base
    unsigned aP   = sb + OFF_P + (unsigned)((rg * 16 + lrow) * PS2 * 2) + lk8b;
    unsigned voff = (unsigned)(lrow * KQS * 2) + (unsigned)(cg * 256); // + buffer base

    // load Q tile (32 x 512 fp16)
    #pragma unroll
    for (int i0 = 0; i0 < 8; i0++) {
        int i = tid + i0 * 256;
        int r = i >> 6, c8 = (i & 63) << 3;
        *(uint4*)&Qs[r * KQS + c8] = *(const uint4*)&X[(size_t)(q0 + r) * DD + c8];
    }

    float acc[16][4];
    #pragma unroll
    for (int i = 0; i < 16; i++) { acc[i][0] = acc[i][1] = acc[i][2] = acc[i][3] = 0.f; }
    float lsum0 = 0.f, lsum1 = 0.f;

    int par0 = (rg * 16 + g4) * PS2;
    int par1 = (rg * 16 + g4 + 8) * PS2;
    int pc = cg * 8 + 2 * tig;

    int kb0 = (qb >= WTILES) ? qb - WTILES : 0;
    attn_fillK(sb + OFF_K0, X, kb0, tid);     // prologue prefetch

    for (int kb = kb0; kb <= qb; kb++) {
        int cur = (kb - kb0) & 1;
        unsigned kbase = sb + (cur ? OFF_K1 : OFF_K0);
        __syncthreads();                      // prev iter's reads of the other buffer done
        if (kb < qb) {
            attn_fillK(sb + (cur ? OFF_K0 : OFF_K1), X, kb + 1, tid);
            CPA_WAIT1();                      // current buffer's group complete
        } else {
            CPA_WAIT0();
        }
        __syncthreads();                      // K tile visible to all warps

        // scores: S = Q K^T, 4 independent accumulator chains
        float s4[4][4];
        #pragma unroll
        for (int i = 0; i < 4; i++) { s4[i][0] = s4[i][1] = s4[i][2] = s4[i][3] = 0.f; }
        unsigned bK = kbase + koff;
        #pragma unroll 8
        for (int ks2 = 0; ks2 < 32; ks2++) {
            unsigned o = ks2 * 32;
            unsigned ah[4], bh[2];
            ldmx4(ah, aQ + o);
            ldmx2(bh, bK + o);
            mma_f16(s4[ks2 & 3], ah, bh);
        }
        float sc[4];
        #pragma unroll
        for (int i = 0; i < 4; i++)
            sc[i] = (s4[0][i] + s4[1][i]) + (s4[2][i] + s4[3][i]);

        int r0 = q0 + rg * 16 + g4, r1 = r0 + 8;
        int c0 = kb * 32 + cg * 8 + 2 * tig, c1 = c0 + 1;
        float p0 = (r0 >= c0) ? __expf(sc[0] - DECAYF * (float)(r0 - c0)) : 0.f;
        float p1 = (r0 >= c1) ? __expf(sc[1] - DECAYF * (float)(r0 - c1)) : 0.f;
        float p2 = (r1 >= c0) ? __expf(sc[2] - DECAYF * (float)(r1 - c0)) : 0.f;
        float p3 = (r1 >= c1) ? __expf(sc[3] - DECAYF * (float)(r1 - c1)) : 0.f;
        lsum0 += p0 + p1;
        lsum1 += p2 + p3;
        *(unsigned*)&Ps[par0 + pc] = packh2(p0, p1);
        *(unsigned*)&Ps[par1 + pc] = packh2(p2, p3);
        __syncthreads();                      // P tile ready

        // PV: O += P V (16 independent chains)
        unsigned bV = kbase + voff;
        #pragma unroll
        for (int ks2 = 0; ks2 < 2; ks2++) {
            unsigned ah[4];
            ldmx4(ah, aP + ks2 * 32);
            unsigned vh = bV + (unsigned)(ks2 * 16 * KQS * 2);
            #pragma unroll
            for (int nf = 0; nf < 16; nf++) {
                unsigned bh[2];
                ldmx2t(bh, vh + nf * 16);
                mma_f16(acc[nf], ah, bh);
            }
        }
    }

    lsum0 += __shfl_xor_sync(0xffffffffu, lsum0, 1);
    lsum0 += __shfl_xor_sync(0xffffffffu, lsum0, 2);
    lsum1 += __shfl_xor_sync(0xffffffffu, lsum1, 1);
    lsum1 += __shfl_xor_sync(0xffffffffu, lsum1, 2);
    __syncthreads();
    if (tig == 0) {
        redl[cg * 32 + rg * 16 + g4]     = lsum0;
        redl[cg * 32 + rg * 16 + g4 + 8] = lsum1;
    }
    __syncthreads();
    int row0 = rg * 16 + g4;
    float lt0 = redl[row0] + redl[32 + row0] + redl[64 + row0] + redl[96 + row0];
    float lt1 = redl[row0 + 8] + redl[32 + row0 + 8] + redl[64 + row0 + 8] + redl[96 + row0 + 8];
    float li0 = 1.f / lt0;
    float li1 = 1.f / lt1;

    size_t orow0 = (size_t)(n * LQ + q0 + row0) * (2 * DD);
    size_t orow1 = orow0 + (size_t)8 * (2 * DD);
    #pragma unroll
    for (int nf = 0; nf < 16; nf++) {
        int col = zb * DD + cg * 128 + nf * 8 + 2 * tig;
        *(unsigned*)&g_cat[orow0 + col] = packh2(acc[nf][0] * li0, acc[nf][1] * li0);
        *(unsigned*)&g_cat[orow1 + col] = packh2(acc[nf][2] * li1, acc[nf][3] * li1);
    }
}

// ---------------------------------------------------------------------------
// fusion: out[16384,512] = cat @ W^T + bias, fp16
// CTA 128x64, warp 32x32, K-chunk 64, double-buffered cp.async, 4 CTAs/SM
// ---------------------------------------------------------------------------
__device__ __forceinline__ void fus_fill(unsigned sbuf, int kc, int bm, int bn, int tid) {
    #pragma unroll
    for (int i = 0; i < 4; i++) {
        int idx = tid + i * 256;
        int r = idx >> 3, c8 = (idx & 7) << 3;
        cpa16(sbuf + F_A + (unsigned)(r * FROWB + c8 * 2),
              &g_cat[(size_t)(bm + r) * 1024 + kc * 64 + c8]);
    }
    #pragma unroll
    for (int i = 0; i < 2; i++) {
        int idx = tid + i * 256;
        int r = idx >> 3, c8 = (idx & 7) << 3;
        cpa16(sbuf + F_B + (unsigned)(r * FROWB + c8 * 2),
              &g_W[(size_t)(bn + r) * 1024 + kc * 64 + c8]);
    }
    CPA_COMMIT();
}

__global__ void __launch_bounds__(256, 4) fusion_kernel(const float* __restrict__ bias,
                                                        float* __restrict__ out) {
    extern __shared__ char fsm[];
    unsigned sb = (unsigned)__cvta_generic_to_shared(fsm);
    int tid = threadIdx.x;
    int w = tid >> 5, lane = tid & 31;
    int g4 = lane >> 2, tig = lane & 3, lane7 = lane & 7;
    int rg = w & 3, cg = w >> 2;
    int bm = blockIdx.x * 128;
    int bn = blockIdx.y * 64;
    int lrow = lane7 + ((lane >> 3) & 1) * 8;
    int lk8b = (lane >> 4) * 16;
    int bk8b = ((lane >> 3) & 1) * 16;

    float acc[2][4][4];
    #pragma unroll
    for (int t = 0; t < 2; t++)
        #pragma unroll
        for (int nf = 0; nf < 4; nf++) {
            acc[t][nf][0] = 0.f; acc[t][nf][1] = 0.f;
            acc[t][nf][2] = 0.f; acc[t][nf][3] = 0.f;
        }

    fus_fill(sb, 0, bm, bn, tid);
    fus_fill(sb + F_BUF, 1, bm, bn, tid);

    unsigned aoff0 = (unsigned)((rg * 32 + lrow) * FROWB) + lk8b;
    unsigned aoff1 = (unsigned)((rg * 32 + 16 + lrow) * FROWB) + lk8b;
    unsigned boffs[4];
    #pragma unroll
    for (int nf = 0; nf < 4; nf++)
        boffs[nf] = (unsigned)((cg * 32 + nf * 8 + lane7) * FROWB) + bk8b;

    for (int c = 0; c < FNCH; c++) {
        unsigned base = sb + (unsigned)(c & 1) * F_BUF;
        if (c == FNCH - 1) { CPA_WAIT0(); } else { CPA_WAIT1(); }
        __syncthreads();

        #pragma unroll
        for (int ks = 0; ks < 4; ks++) {
            unsigned ko = (unsigned)(ks * 32);
            unsigned ah0[4], ah1[4];
            ldmx4(ah0, base + F_A + aoff0 + ko);
            ldmx4(ah1, base + F_A + aoff1 + ko);
            unsigned bh[4][2];
            #pragma unroll
            for (int nf = 0; nf < 4; nf++)
                ldmx2(bh[nf], base + F_B + boffs[nf] + ko);
            #pragma unroll
            for (int nf = 0; nf < 4; nf++) {
                mma_f16(acc[0][nf], ah0, bh[nf]);
                mma_f16(acc[1][nf], ah1, bh[nf]);
            }
        }
        __syncthreads();
        if (c + 2 < FNCH) fus_fill(base, c + 2, bm, bn, tid);
    }

    #pragma unroll
    for (int t = 0; t < 2; t++) {
        int orow0 = bm + rg * 32 + t * 16 + g4;
        int orow1 = orow0 + 8;
        #pragma unroll
        for (int nf = 0; nf < 4; nf++) {
            int col = bn + cg * 32 + nf * 8 + 2 * tig;
            float b0v = bias[col], b1v = bias[col + 1];
            *(float2*)&out[(size_t)orow0 * 512 + col] =
                make_float2(acc[t][nf][0] + b0v, acc[t][nf][1] + b1v);
            *(float2*)&out[(size_t)orow1 * 512 + col] =
                make_float2(acc[t][nf][2] + b0v, acc[t][nf][3] + b1v);
        }
    }
}

// ---------------------------------------------------------------------------
extern "C" void kernel_launch(void* const* d_in, const int* in_sizes, int n_in,
                              void* d_out, int out_size) {
    const float* x  = (const float*)d_in[0];
    const float* w3 = (const float*)d_in[1];
    const float* w5 = (const float*)d_in[2];
    const float* fw = (const float*)d_in[3];
    const float* fb = (const float*)d_in[4];
    float* out = (float*)d_out;

    prep_kernel<<<NB * LQ / 8, 256>>>(x, w3, w5, fw);

    cudaFuncSetAttribute(attn_kernel,
                         cudaFuncAttributeMaxDynamicSharedMemorySize, SMEM_ATTN);
    dim3 ga(LQ / 32, NB, 2);
    attn_kernel<<<ga, 256, SMEM_ATTN>>>();

    cudaFuncSetAttribute(fusion_kernel,
                         cudaFuncAttributeMaxDynamicSharedMemorySize, SMEM_FUS);
    dim3 gf((NB * LQ) / 128, DD / 64);
    fusion_kernel<<<gf, 256, SMEM_FUS>>>(fb, out);
}

// round 17
// speedup vs baseline: 1.2602x; 1.0569x over previous
#include <cuda_runtime.h>
#include <cuda_fp16.h>
#include <math.h>

#define NB 8
#define LQ 2048
#define DD 512
#define DECAYF 0.2f
#define WTILES 2     // window: current + 2 previous 32-row tiles (tail mass < 3.4e-5)
#define KQS 520      // Q/K smem stride (fp16 elems) -> 1040 B
#define PS2 40       // P smem stride (fp16 elems) -> 80 B

// attn smem byte offsets (fp16, 32-row Q, double-buffered 32-row K)
#define OFF_Q  0
#define OFF_K0 33280
#define OFF_K1 66560
#define OFF_P  99840
#define OFF_RED 102400
#define SMEM_ATTN (OFF_RED + 512)

// fusion tiling: CTA 128x64, warp 32x32, K-chunk 64, double-buffered cp.async
#define FROWB 144
#define F_A 0
#define F_B 18432
#define F_BUF 27648
#define SMEM_FUS (2 * F_BUF)
#define FNCH 16

// Scratch (device globals: allocation-free per harness rules)
__device__ __half g_Xs[NB * LQ * DD];
__device__ __half g_Xt[NB * LQ * DD];
__device__ __half g_cat[NB * LQ * 2 * DD];
__device__ __half g_W[DD * 2 * DD];

// ---------------------------------------------------------------------------
// mma / ldmatrix / cp.async helpers (legacy mma.sync — tcgen05 rejected by
// this toolchain's sm_103 non-'a' target)
// ---------------------------------------------------------------------------
__device__ __forceinline__ void ldmx4(unsigned* r, unsigned a) {
    asm volatile("ldmatrix.sync.aligned.m8n8.x4.shared.b16 {%0,%1,%2,%3}, [%4];"
        : "=r"(r[0]), "=r"(r[1]), "=r"(r[2]), "=r"(r[3]) : "r"(a));
}
__device__ __forceinline__ void ldmx2(unsigned* r, unsigned a) {
    asm volatile("ldmatrix.sync.aligned.m8n8.x2.shared.b16 {%0,%1}, [%2];"
        : "=r"(r[0]), "=r"(r[1]) : "r"(a));
}
__device__ __forceinline__ void ldmx2t(unsigned* r, unsigned a) {
    asm volatile("ldmatrix.sync.aligned.m8n8.x2.trans.shared.b16 {%0,%1}, [%2];"
        : "=r"(r[0]), "=r"(r[1]) : "r"(a));
}
__device__ __forceinline__ void mma_f16(float* c, const unsigned* a, const unsigned* b) {
    asm volatile("mma.sync.aligned.m16n8k16.row.col.f32.f16.f16.f32 "
        "{%0,%1,%2,%3}, {%4,%5,%6,%7}, {%8,%9}, {%0,%1,%2,%3};"
        : "+f"(c[0]), "+f"(c[1]), "+f"(c[2]), "+f"(c[3])
        : "r"(a[0]), "r"(a[1]), "r"(a[2]), "r"(a[3]), "r"(b[0]), "r"(b[1]));
}
__device__ __forceinline__ void cpa16(unsigned saddr, const void* g) {
    asm volatile("cp.async.cg.shared.global [%0], [%1], 16;"
        :: "r"(saddr), "l"(g) : "memory");
}
#define CPA_COMMIT() asm volatile("cp.async.commit_group;" ::: "memory")
#define CPA_WAIT1()  asm volatile("cp.async.wait_group 1;" ::: "memory")
#define CPA_WAIT0()  asm volatile("cp.async.wait_group 0;" ::: "memory")

__device__ __forceinline__ unsigned packh2(float a, float b) {
    __half2 h = __floats2half2_rn(a, b);
    return *(unsigned*)&h;
}
__device__ __forceinline__ float warpSum(float v) {
    #pragma unroll
    for (int o = 16; o > 0; o >>= 1) v += __shfl_xor_sync(0xffffffffu, v, o);
    return v;
}

// ---------------------------------------------------------------------------
// Scalar dynamic routing from the capsule Gram matrix (exact reformulation):
// s = c0 u0 + c1 u1; all dots reduce to the 3 Gram entries.
// Returns the final (c0*scl, c1*scl) so v = o0*u0 + o1*u1.
// ---------------------------------------------------------------------------
__device__ __forceinline__ void routing_gram(float d00, float d01, float d11,
                                             float& o0, float& o1) {
    float b0 = 0.f, b1 = 0.f, c0 = 0.5f, c1 = 0.5f, scl = 0.f;
    #pragma unroll
    for (int it = 0; it < 3; it++) {
        float mx = fmaxf(b0, b1);
        float e0 = __expf(b0 - mx), e1 = __expf(b1 - mx);
        float inv = 1.f / (e0 + e1);
        c0 = e0 * inv; c1 = e1 * inv;
        float n2 = c0 * c0 * d00 + 2.f * c0 * c1 * d01 + c1 * c1 * d11;
        float nrm = sqrtf(n2);
        scl = n2 / ((1.f + n2) * (nrm + 1e-9f));
        if (it < 2) {
            b0 += scl * (c0 * d00 + c1 * d01);
            b1 += scl * (c0 * d01 + c1 * d11);
        }
    }
    o0 = scl * c0;
    o1 = scl * c1;
}

// ---------------------------------------------------------------------------
// Kernel 1: convs + Gram-based routing + folded W fp16 conversion
// grid = 2048 x 256: warp-per-row (16 channels/lane), 6 warp reductions total
// ---------------------------------------------------------------------------
__global__ void __launch_bounds__(256) prep_kernel(const float* __restrict__ x,
                                                   const float* __restrict__ w3,
                                                   const float* __restrict__ w5,
                                                   const float* __restrict__ W) {
    // folded wsplit: one W element per thread (grid exactly covers 512*1024)
    int widx = blockIdx.x * 256 + threadIdx.x;
    g_W[widx] = __float2half(W[widx]);

    int wid = threadIdx.x >> 5, lane = threadIdx.x & 31;
    int row = blockIdx.x * 8 + wid;
    int n = row >> 11, l = row & 2047;
    const float* xb = x + (size_t)n * LQ * DD;

    float xv[16], t3[16], t5[16];
    float dxx = 0.f, dx3 = 0.f, dx5 = 0.f, d33 = 0.f, d35 = 0.f, d55 = 0.f;
    #pragma unroll
    for (int i = 0; i < 16; i++) {
        int c = lane + 32 * i;
        float a3 = 0.f, a5 = 0.f, xx = 0.f;
        #pragma unroll
        for (int j = 0; j < 5; j++) {
            int ll = l - 4 + j;
            xx = (ll >= 0) ? __ldg(xb + (size_t)ll * DD + c) : 0.f;
            a5 = fmaf(w5[c * 5 + j], xx, a5);
            if (j >= 2) a3 = fmaf(w3[c * 3 + (j - 2)], xx, a3);
        }
        xv[i] = xx; t3[i] = a3; t5[i] = a5;
        dxx = fmaf(xx, xx, dxx);
        dx3 = fmaf(xx, a3, dx3);
        dx5 = fmaf(xx, a5, dx5);
        d33 = fmaf(a3, a3, d33);
        d35 = fmaf(a3, a5, d35);
        d55 = fmaf(a5, a5, d55);
    }
    dxx = warpSum(dxx); dx3 = warpSum(dx3); dx5 = warpSum(dx5);
    d33 = warpSum(d33); d35 = warpSum(d35); d55 = warpSum(d55);

    // seasonal capsules: u0 = x - t3, u1 = x - t5
    // Gram: d00 = dxx - 2dx3 + d33; d01 = dxx - dx3 - dx5 + d35; d11 = dxx - 2dx5 + d55
    float o0, o1;
    routing_gram(dxx - 2.f * dx3 + d33,
                 dxx - dx3 - dx5 + d35,
                 dxx - 2.f * dx5 + d55, o0, o1);
    #pragma unroll
    for (int i = 0; i < 16; i++) {
        float v = o0 * (xv[i] - t3[i]) + o1 * (xv[i] - t5[i]);
        g_Xs[(size_t)row * DD + lane + 32 * i] = __float2half(v);
    }

    // trend capsules: u0 = t3, u1 = t5; Gram = (d33, d35, d55)
    routing_gram(d33, d35, d55, o0, o1);
    #pragma unroll
    for (int i = 0; i < 16; i++) {
        float v = o0 * t3[i] + o1 * t5[i];
        g_Xt[(size_t)row * DD + lane + 32 * i] = __float2half(v);
    }
}

// ---------------------------------------------------------------------------
// attention: windowed flash, fp16, fixed-shift softmax, cp.async K prefetch,
// 4-way split QK chains. grid=(64, 8, 2), 256 threads, 2 CTAs/SM  (R12 shape)
// ---------------------------------------------------------------------------
__device__ __forceinline__ void attn_fillK(unsigned sdst, const __half* X, int kb, int tid) {
    #pragma unroll
    for (int i0 = 0; i0 < 8; i0++) {
        int i = tid + i0 * 256;
        int r = i >> 6, c8 = (i & 63) << 3;
        cpa16(sdst + (unsigned)(r * KQS * 2 + c8 * 2), &X[(size_t)(kb * 32 + r) * DD + c8]);
    }
    CPA_COMMIT();
}

__global__ void __launch_bounds__(256, 2) attn_kernel() {
    extern __shared__ char smraw[];
    __half* Qs = (__half*)(smraw + OFF_Q);
    __half* Ps = (__half*)(smraw + OFF_P);
    float* redl = (float*)(smraw + OFF_RED);

    int zb = blockIdx.z;
    const __half* X = (zb ? g_Xt : g_Xs) + (size_t)blockIdx.y * LQ * DD;
    int n = blockIdx.y;
    int qb = blockIdx.x;
    int tid = threadIdx.x;
    int w = tid >> 5, lane = tid & 31;
    int g4 = lane >> 2, tig = lane & 3, lane7 = lane & 7;
    int q0 = qb * 32;
    int rg = w & 1, cg = w >> 1;

    unsigned sb = (unsigned)__cvta_generic_to_shared(smraw);
    int lrow = lane7 + ((lane >> 3) & 1) * 8;
    int lk8b = (lane >> 4) * 16;
    int bk8b = ((lane >> 3) & 1) * 16;

    unsigned aQ   = sb + OFF_Q + (unsigned)((rg * 16 + lrow) * KQS * 2) + lk8b;
    unsigned koff = (unsigned)((cg * 8 + lane7) * KQS * 2) + bk8b;     // + buffer base
    unsigned aP   = sb + OFF_P + (unsigned)((rg * 16 + lrow) * PS2 * 2) + lk8b;
    unsigned voff = (unsigned)(lrow * KQS * 2) + (unsigned)(cg * 256); // + buffer base

    // load Q tile (32 x 512 fp16)
    #pragma unroll
    for (int i0 = 0; i0 < 8; i0++) {
        int i = tid + i0 * 256;
        int r = i >> 6, c8 = (i & 63) << 3;
        *(uint4*)&Qs[r * KQS + c8] = *(const uint4*)&X[(size_t)(q0 + r) * DD + c8];
    }

    float acc[16][4];
    #pragma unroll
    for (int i = 0; i < 16; i++) { acc[i][0] = acc[i][1] = acc[i][2] = acc[i][3] = 0.f; }
    float lsum0 = 0.f, lsum1 = 0.f;

    int par0 = (rg * 16 + g4) * PS2;
    int par1 = (rg * 16 + g4 + 8) * PS2;
    int pc = cg * 8 + 2 * tig;

    int kb0 = (qb >= WTILES) ? qb - WTILES : 0;
    attn_fillK(sb + OFF_K0, X, kb0, tid);     // prologue prefetch

    for (int kb = kb0; kb <= qb; kb++) {
        int cur = (kb - kb0) & 1;
        unsigned kbase = sb + (cur ? OFF_K1 : OFF_K0);
        __syncthreads();                      // prev iter's reads of the other buffer done
        if (kb < qb) {
            attn_fillK(sb + (cur ? OFF_K0 : OFF_K1), X, kb + 1, tid);
            CPA_WAIT1();                      // current buffer's group complete
        } else {
            CPA_WAIT0();
        }
        __syncthreads();                      // K tile visible to all warps

        // scores: S = Q K^T, 4 independent accumulator chains
        float s4[4][4];
        #pragma unroll
        for (int i = 0; i < 4; i++) { s4[i][0] = s4[i][1] = s4[i][2] = s4[i][3] = 0.f; }
        unsigned bK = kbase + koff;
        #pragma unroll 8
        for (int ks2 = 0; ks2 < 32; ks2++) {
            unsigned o = ks2 * 32;
            unsigned ah[4], bh[2];
            ldmx4(ah, aQ + o);
            ldmx2(bh, bK + o);
            mma_f16(s4[ks2 & 3], ah, bh);
        }
        float sc[4];
        #pragma unroll
        for (int i = 0; i < 4; i++)
            sc[i] = (s4[0][i] + s4[1][i]) + (s4[2][i] + s4[3][i]);

        int r0 = q0 + rg * 16 + g4, r1 = r0 + 8;
        int c0 = kb * 32 + cg * 8 + 2 * tig, c1 = c0 + 1;
        float p0 = (r0 >= c0) ? __expf(sc[0] - DECAYF * (float)(r0 - c0)) : 0.f;
        float p1 = (r0 >= c1) ? __expf(sc[1] - DECAYF * (float)(r0 - c1)) : 0.f;
        float p2 = (r1 >= c0) ? __expf(sc[2] - DECAYF * (float)(r1 - c0)) : 0.f;
        float p3 = (r1 >= c1) ? __expf(sc[3] - DECAYF * (float)(r1 - c1)) : 0.f;
        lsum0 += p0 + p1;
        lsum1 += p2 + p3;
        *(unsigned*)&Ps[par0 + pc] = packh2(p0, p1);
        *(unsigned*)&Ps[par1 + pc] = packh2(p2, p3);
        __syncthreads();                      // P tile ready

        // PV: O += P V (16 independent chains)
        unsigned bV = kbase + voff;
        #pragma unroll
        for (int ks2 = 0; ks2 < 2; ks2++) {
            unsigned ah[4];
            ldmx4(ah, aP + ks2 * 32);
            unsigned vh = bV + (unsigned)(ks2 * 16 * KQS * 2);
            #pragma unroll
            for (int nf = 0; nf < 16; nf++) {
                unsigned bh[2];
                ldmx2t(bh, vh + nf * 16);
                mma_f16(acc[nf], ah, bh);
            }
        }
    }

    lsum0 += __shfl_xor_sync(0xffffffffu, lsum0, 1);
    lsum0 += __shfl_xor_sync(0xffffffffu, lsum0, 2);
    lsum1 += __shfl_xor_sync(0xffffffffu, lsum1, 1);
    lsum1 += __shfl_xor_sync(0xffffffffu, lsum1, 2);
    __syncthreads();
    if (tig == 0) {
        redl[cg * 32 + rg * 16 + g4]     = lsum0;
        redl[cg * 32 + rg * 16 + g4 + 8] = lsum1;
    }
    __syncthreads();
    int row0 = rg * 16 + g4;
    float lt0 = redl[row0] + redl[32 + row0] + redl[64 + row0] + redl[96 + row0];
    float lt1 = redl[row0 + 8] + redl[32 + row0 + 8] + redl[64 + row0 + 8] + redl[96 + row0 + 8];
    float li0 = 1.f / lt0;
    float li1 = 1.f / lt1;

    size_t orow0 = (size_t)(n * LQ + q0 + row0) * (2 * DD);
    size_t orow1 = orow0 + (size_t)8 * (2 * DD);
    #pragma unroll
    for (int nf = 0; nf < 16; nf++) {
        int col = zb * DD + cg * 128 + nf * 8 + 2 * tig;
        *(unsigned*)&g_cat[orow0 + col] = packh2(acc[nf][0] * li0, acc[nf][1] * li0);
        *(unsigned*)&g_cat[orow1 + col] = packh2(acc[nf][2] * li1, acc[nf][3] * li1);
    }
}

// ---------------------------------------------------------------------------
// fusion: out[16384,512] = cat @ W^T + bias, fp16
// CTA 128x64, warp 32x32, K-chunk 64, double-buffered cp.async, 4 CTAs/SM
// ---------------------------------------------------------------------------
__device__ __forceinline__ void fus_fill(unsigned sbuf, int kc, int bm, int bn, int tid) {
    #pragma unroll
    for (int i = 0; i < 4; i++) {
        int idx = tid + i * 256;
        int r = idx >> 3, c8 = (idx & 7) << 3;
        cpa16(sbuf + F_A + (unsigned)(r * FROWB + c8 * 2),
              &g_cat[(size_t)(bm + r) * 1024 + kc * 64 + c8]);
    }
    #pragma unroll
    for (int i = 0; i < 2; i++) {
        int idx = tid + i * 256;
        int r = idx >> 3, c8 = (idx & 7) << 3;
        cpa16(sbuf + F_B + (unsigned)(r * FROWB + c8 * 2),
              &g_W[(size_t)(bn + r) * 1024 + kc * 64 + c8]);
    }
    CPA_COMMIT();
}

__global__ void __launch_bounds__(256, 4) fusion_kernel(const float* __restrict__ bias,
                                                        float* __restrict__ out) {
    extern __shared__ char fsm[];
    unsigned sb = (unsigned)__cvta_generic_to_shared(fsm);
    int tid = threadIdx.x;
    int w = tid >> 5, lane = tid & 31;
    int g4 = lane >> 2, tig = lane & 3, lane7 = lane & 7;
    int rg = w & 3, cg = w >> 2;
    int bm = blockIdx.x * 128;
    int bn = blockIdx.y * 64;
    int lrow = lane7 + ((lane >> 3) & 1) * 8;
    int lk8b = (lane >> 4) * 16;
    int bk8b = ((lane >> 3) & 1) * 16;

    float acc[2][4][4];
    #pragma unroll
    for (int t = 0; t < 2; t++)
        #pragma unroll
        for (int nf = 0; nf < 4; nf++) {
            acc[t][nf][0] = 0.f; acc[t][nf][1] = 0.f;
            acc[t][nf][2] = 0.f; acc[t][nf][3] = 0.f;
        }

    fus_fill(sb, 0, bm, bn, tid);
    fus_fill(sb + F_BUF, 1, bm, bn, tid);

    unsigned aoff0 = (unsigned)((rg * 32 + lrow) * FROWB) + lk8b;
    unsigned aoff1 = (unsigned)((rg * 32 + 16 + lrow) * FROWB) + lk8b;
    unsigned boffs[4];
    #pragma unroll
    for (int nf = 0; nf < 4; nf++)
        boffs[nf] = (unsigned)((cg * 32 + nf * 8 + lane7) * FROWB) + bk8b;

    for (int c = 0; c < FNCH; c++) {
        unsigned base = sb + (unsigned)(c & 1) * F_BUF;
        if (c == FNCH - 1) { CPA_WAIT0(); } else { CPA_WAIT1(); }
        __syncthreads();

        #pragma unroll
        for (int ks = 0; ks < 4; ks++) {
            unsigned ko = (unsigned)(ks * 32);
            unsigned ah0[4], ah1[4];
            ldmx4(ah0, base + F_A + aoff0 + ko);
            ldmx4(ah1, base + F_A + aoff1 + ko);
            unsigned bh[4][2];
            #pragma unroll
            for (int nf = 0; nf < 4; nf++)
                ldmx2(bh[nf], base + F_B + boffs[nf] + ko);
            #pragma unroll
            for (int nf = 0; nf < 4; nf++) {
                mma_f16(acc[0][nf], ah0, bh[nf]);
                mma_f16(acc[1][nf], ah1, bh[nf]);
            }
        }
        __syncthreads();
        if (c + 2 < FNCH) fus_fill(base, c + 2, bm, bn, tid);
    }

    #pragma unroll
    for (int t = 0; t < 2; t++) {
        int orow0 = bm + rg * 32 + t * 16 + g4;
        int orow1 = orow0 + 8;
        #pragma unroll
        for (int nf = 0; nf < 4; nf++) {
            int col = bn + cg * 32 + nf * 8 + 2 * tig;
            float b0v = bias[col], b1v = bias[col + 1];
            *(float2*)&out[(size_t)orow0 * 512 + col] =
                make_float2(acc[t][nf][0] + b0v, acc[t][nf][1] + b1v);
            *(float2*)&out[(size_t)orow1 * 512 + col] =
                make_float2(acc[t][nf][2] + b0v, acc[t][nf][3] + b1v);
        }
    }
}

// ---------------------------------------------------------------------------
extern "C" void kernel_launch(void* const* d_in, const int* in_sizes, int n_in,
                              void* d_out, int out_size) {
    const float* x  = (const float*)d_in[0];
    const float* w3 = (const float*)d_in[1];
    const float* w5 = (const float*)d_in[2];
    const float* fw = (const float*)d_in[3];
    const float* fb = (const float*)d_in[4];
    float* out = (float*)d_out;

    prep_kernel<<<NB * LQ / 8, 256>>>(x, w3, w5, fw);

    cudaFuncSetAttribute(attn_kernel,
                         cudaFuncAttributeMaxDynamicSharedMemorySize, SMEM_ATTN);
    dim3 ga(LQ / 32, NB, 2);
    attn_kernel<<<ga, 256, SMEM_ATTN>>>();

    cudaFuncSetAttribute(fusion_kernel,
                         cudaFuncAttributeMaxDynamicSharedMemorySize, SMEM_FUS);
    dim3 gf((NB * LQ) / 128, DD / 64);
    fusion_kernel<<<gf, 256, SMEM_FUS>>>(fb, out);
}